// round 9
// baseline (speedup 1.0000x reference)
#include <cuda_runtime.h>
#include <cuda_fp16.h>
#include <cstdint>

// ============================================================================
// DistNet: out[n] = sigmoid((max(0, ||x||^2 + min_p(||p||^2 - 2 x.p)) + alpha)/beta)
// R9: 3-stage pair-private cp.async pipeline (wait_group 1 -> each copy gets
// a 2-iteration landing window). Stage-2 buffers for pairs 0/1 overlay the
// dead X-tile smem; ||p||^2 loaded once to a static region (no re-copy).
// fp16 m16n8k16 f16-acc HMMA, 4 chains, half2 min-fold (R8 core).
// ============================================================================

static constexpr int NROWS  = 65536;
static constexpr int DIM    = 128;
static constexpr int NPTS   = 2048;
static constexpr int MTILE  = 64;
static constexpr int SUBPTS = 32;            // points per sub-chunk
static constexpr int NSUB   = 512 / SUBPTS;  // 16 sub-chunks per pair

#define LOG1000F 6.9077542789816375f

__device__ __align__(16) __half g_pts[NPTS * DIM];  // fp16 points, K-major
__device__ __align__(16) __half g_pn[NPTS];         // ||p||^2 (fp16)

// smem layout (dynamic)
static constexpr int OFF_X    = 0;        // 16384: X tile, later stage2 of pairs 0/1
static constexpr int OFF_B    = 16384;    // 65536: stages 0,1 for all 4 pairs
static constexpr int OFF_S2X  = 81920;    // 16384: stage2 for pairs 2,3
static constexpr int OFF_PN   = 98304;    // 4096:  ||p||^2, 1KB per pair (static)
static constexpr int OFF_XN   = 102400;   // 256:   ||x||^2 per row
static constexpr int OFF_MIN  = 102656;   // 768:   min-combine buffer
static constexpr int SMEM_BYTES = 103552; // <= ~113KB -> occupancy 2

static constexpr int BUFBYTES = SUBPTS * 256;  // 8192 per stage buffer

// ---------------------------------------------------------------------------
__device__ __forceinline__ uint32_t smem_u32(const void* p) {
    uint32_t a;
    asm("{ .reg .u64 t; cvta.to.shared.u64 t, %1; cvt.u32.u64 %0, t; }"
        : "=r"(a) : "l"(p));
    return a;
}

__device__ __forceinline__ void cp_async16(uint32_t dst, const void* src) {
    asm volatile("cp.async.cg.shared.global [%0], [%1], 16;"
                 :: "r"(dst), "l"(src) : "memory");
}

#define LDMATRIX_X4(R, ADDR)                                                   \
    asm volatile("ldmatrix.sync.aligned.m8n8.x4.shared.b16 {%0,%1,%2,%3}, [%4];" \
                 : "=r"((R)[0]), "=r"((R)[1]), "=r"((R)[2]), "=r"((R)[3])       \
                 : "r"(ADDR))

#define MMA16816H(C, A, B0, B1)                                                \
    asm volatile("mma.sync.aligned.m16n8k16.row.col.f16.f16.f16.f16 "          \
                 "{%0,%1}, {%2,%3,%4,%5}, {%6,%7}, {%0,%1};"                   \
                 : "+r"((C)[0]), "+r"((C)[1])                                  \
                 : "r"((A)[0]), "r"((A)[1]), "r"((A)[2]), "r"((A)[3]),         \
                   "r"(B0), "r"(B1))

// ---------------------------------------------------------------------------
// Prep: points f32 -> fp16 row-major + ||p||^2 (fp16)
__global__ void distnet_prep(const float* __restrict__ pts) {
    int p = blockIdx.x;
    int t = threadIdx.x;  // 128 = DIM
    float v = pts[p * DIM + t];
    g_pts[p * DIM + t] = __float2half(v);
    float s = v * v;
#pragma unroll
    for (int o = 16; o > 0; o >>= 1) s += __shfl_xor_sync(0xffffffffu, s, o);
    __shared__ float ws[4];
    if ((t & 31) == 0) ws[t >> 5] = s;
    __syncthreads();
    if (t == 0) g_pn[p] = __float2half(ws[0] + ws[1] + ws[2] + ws[3]);
}

// ---------------------------------------------------------------------------
// Pair-scope async copy of one 32-point sub-chunk (8KB). tp in [0,64).
// Swizzle: 16B unit c of point row n -> n*256 + ((c ^ (n&7))*16).
__device__ __forceinline__ void issue_sub(uint32_t dst, int pair, int sub, int tp) {
    const char* src = (const char*)g_pts + ((size_t)pair * 512 + sub * SUBPTS) * 256;
#pragma unroll
    for (int u = 0; u < 8; u++) {
        int i = tp + u * 64;             // 0..511 16B units
        int n = i >> 4, c = i & 15;
        cp_async16(dst + n * 256 + ((c ^ (n & 7)) * 16), src + i * 16);
    }
    asm volatile("cp.async.commit_group;" ::: "memory");
}

// ---------------------------------------------------------------------------
__global__ void __launch_bounds__(256, 2)
distnet_main(const float* __restrict__ x, const float* __restrict__ beta_raw,
             float* __restrict__ out) {
    extern __shared__ char smem[];
    const uint32_t sb = smem_u32(smem);
    const int tid   = threadIdx.x;
    const int lane  = tid & 31;
    const int wid   = tid >> 5;        // 0..7
    const int mhalf = wid & 1;         // m32 half of the 64-row tile
    const int pair  = wid >> 1;        // 0..3, owns points [512*pair, +512)
    const int tp    = tid & 63;        // thread index within pair
    const int row0  = blockIdx.x * MTILE;

    // stage buffer bases for this pair
    const uint32_t st0 = sb + OFF_B + pair * (2 * BUFBYTES);
    const uint32_t st1 = st0 + BUFBYTES;
    const uint32_t st2 = (pair < 2) ? (sb + OFF_X + pair * BUFBYTES)
                                    : (sb + OFF_S2X + (pair - 2) * BUFBYTES);

    // prologue copies: g0 = pn (1KB) + sub0 -> st0 ; g1 = sub1 -> st1
    cp_async16(sb + OFF_PN + pair * 1024 + tp * 16,
               (const char*)(g_pn + pair * 512) + tp * 16);
    issue_sub(st0, pair, 0, tp);       // commits g0 (includes pn copy)
    issue_sub(st1, pair, 1, tp);       // commits g1

    // ---- X tile: 64 rows x 256B fp16, 4 threads per row + ||x||^2
    {
        int sub = tid & 3;
        int r   = tid >> 2;            // 0..63
        const float4* src = (const float4*)(x + (size_t)(row0 + r) * DIM);
        float s = 0.f;
#pragma unroll
        for (int j = 0; j < 4; j++) {
            int c = j * 4 + sub;       // 16B fp16 unit
            float4 v0 = src[c * 2], v1 = src[c * 2 + 1];
            s += v0.x * v0.x + v0.y * v0.y + v0.z * v0.z + v0.w * v0.w;
            s += v1.x * v1.x + v1.y * v1.y + v1.z * v1.z + v1.w * v1.w;
            __half2 p0 = __floats2half2_rn(v0.x, v0.y);
            __half2 p1 = __floats2half2_rn(v0.z, v0.w);
            __half2 p2 = __floats2half2_rn(v1.x, v1.y);
            __half2 p3 = __floats2half2_rn(v1.z, v1.w);
            uint4 pk;
            pk.x = *(uint32_t*)&p0; pk.y = *(uint32_t*)&p1;
            pk.z = *(uint32_t*)&p2; pk.w = *(uint32_t*)&p3;
            *(uint4*)(smem + OFF_X + r * 256 + ((c ^ (r & 7)) * 16)) = pk;
        }
        s += __shfl_xor_sync(0xffffffffu, s, 1);
        s += __shfl_xor_sync(0xffffffffu, s, 2);
        if (sub == 0) ((float*)(smem + OFF_XN))[r] = s;
    }
    __syncthreads();

    // ---- A fragments: warp owns rows mhalf*32..+31; load once to registers
    uint32_t afr[2][8][4];
    {
        int ar = lane & 15, ah = lane >> 4;
#pragma unroll
        for (int mt = 0; mt < 2; mt++) {
            int r = mhalf * 32 + mt * 16 + ar;
#pragma unroll
            for (int k = 0; k < 8; k++) {
                uint32_t addr = sb + OFF_X + r * 256 + (((2 * k + ah) ^ (r & 7)) * 16);
                LDMATRIX_X4(afr[mt][k], addr);
            }
        }
    }
    __syncthreads();   // all A-frag reads of the X region done -> stage2 may overlay

    const int q  = lane & 3;   // col pair within n8
    const int rp = lane >> 2;  // row within 8
    const uint32_t br_ = lane & 7, bh = lane >> 3;  // B ldmatrix lane mapping
    const int barid = pair + 1;
    const __half2* pnp = (const __half2*)(smem + OFF_PN + pair * 1024);

    const __half2 mtwo = __float2half2_rn(-2.0f);
    const __half2 biginit = __float2half2_rn(60000.0f);
    __half2 rmin2[4] = {biginit, biginit, biginit, biginit};

    uint32_t stages[3] = {st0, st1, st2};

    // ---- mainloop: 3-stage pipeline, wait_group 1 (2-iteration copy window)
#pragma unroll 1
    for (int i = 0; i < NSUB; i++) {
        asm volatile("cp.async.wait_group 1;" ::: "memory");       // copy i landed
        asm volatile("bar.sync %0, 64;" :: "r"(barid) : "memory"); // pair-wide
        if (i + 2 < NSUB)
            issue_sub(stages[(i + 2) % 3], pair, i + 2, tp);       // stage of sub i-1

        const uint32_t buf = stages[i % 3];
        const uint32_t bl  = buf + br_ * 256;
        const __half2* pnb = pnp + i * 16;   // 32 pts = 16 half2 per sub-chunk
#pragma unroll
        for (int g = 0; g < 4; g++) {   // 4 n8-groups of this sub-chunk
            uint32_t bfr[4][4];
#pragma unroll
            for (int kk = 0; kk < 4; kk++) {
                uint32_t addr = bl + g * 2048 + (((4 * kk + bh) ^ br_) * 16);
                LDMATRIX_X4(bfr[kk], addr);
            }
            uint32_t aE0[2] = {0u, 0u}, aO0[2] = {0u, 0u};
            uint32_t aE1[2] = {0u, 0u}, aO1[2] = {0u, 0u};
#pragma unroll
            for (int kk = 0; kk < 4; kk++) {
                MMA16816H(aE0, afr[0][2 * kk],     bfr[kk][0], bfr[kk][1]);
                MMA16816H(aE1, afr[1][2 * kk],     bfr[kk][0], bfr[kk][1]);
                MMA16816H(aO0, afr[0][2 * kk + 1], bfr[kk][2], bfr[kk][3]);
                MMA16816H(aO1, afr[1][2 * kk + 1], bfr[kk][2], bfr[kk][3]);
            }
            __half2 s00 = __hadd2(*(__half2*)&aE0[0], *(__half2*)&aO0[0]);
            __half2 s01 = __hadd2(*(__half2*)&aE0[1], *(__half2*)&aO0[1]);
            __half2 s10 = __hadd2(*(__half2*)&aE1[0], *(__half2*)&aO1[0]);
            __half2 s11 = __hadd2(*(__half2*)&aE1[1], *(__half2*)&aO1[1]);
            __half2 pp = pnb[g * 4 + q];
            rmin2[0] = __hmin2(rmin2[0], __hfma2(mtwo, s00, pp));
            rmin2[1] = __hmin2(rmin2[1], __hfma2(mtwo, s01, pp));
            rmin2[2] = __hmin2(rmin2[2], __hfma2(mtwo, s10, pp));
            rmin2[3] = __hmin2(rmin2[3], __hfma2(mtwo, s11, pp));
        }
    }

    // ---- reduce across the quad (4 col-pairs = 8 cols) within each warp
    float rmin[4];
#pragma unroll
    for (int i = 0; i < 4; i++) {
        uint32_t v = *(uint32_t*)&rmin2[i];
        uint32_t v1 = __shfl_xor_sync(0xffffffffu, v, 1);
        __half2 h = __hmin2(*(__half2*)&v, *(__half2*)&v1);
        uint32_t hv = *(uint32_t*)&h;
        uint32_t v2 = __shfl_xor_sync(0xffffffffu, hv, 2);
        h = __hmin2(h, *(__half2*)&v2);
        rmin[i] = fminf(__low2float(h), __high2float(h));
    }

    // ---- combine the four pairs via smem, then epilogue
    float* minbuf = (float*)(smem + OFF_MIN);   // [3][64]
    if (pair > 0 && q == 0) {
#pragma unroll
        for (int i = 0; i < 4; i++)
            minbuf[(pair - 1) * 64 + mhalf * 32 + i * 8 + rp] = rmin[i];
    }
    __syncthreads();
    if (pair == 0 && q == 0) {
        const float* xn_s = (const float*)(smem + OFF_XN);
        float brv  = beta_raw[0];
        float beta = fmaxf(brv, 0.f) + log1pf(__expf(-fabsf(brv)));  // softplus
#pragma unroll
        for (int i = 0; i < 4; i++) {
            int rl = mhalf * 32 + i * 8 + rp;
            float mn = rmin[i];
            mn = fminf(mn, minbuf[rl]);
            mn = fminf(mn, minbuf[64 + rl]);
            mn = fminf(mn, minbuf[128 + rl]);
            float md  = fmaxf(xn_s[rl] + mn, 0.f);
            float arg = (md - beta * LOG1000F) / beta;
            out[row0 + rl] = 1.f / (1.f + __expf(-arg));
        }
    }
}

// ---------------------------------------------------------------------------
extern "C" void kernel_launch(void* const* d_in, const int* in_sizes, int n_in,
                              void* d_out, int out_size) {
    const float* x    = (const float*)d_in[0];   // [65536,128]
    const float* pts  = (const float*)d_in[1];   // [2048,128]
    const float* braw = (const float*)d_in[2];   // [1]
    float* out = (float*)d_out;                  // [65536]

    cudaFuncSetAttribute(distnet_main, cudaFuncAttributeMaxDynamicSharedMemorySize,
                         SMEM_BYTES);

    distnet_prep<<<NPTS, DIM>>>(pts);
    distnet_main<<<NROWS / MTILE, 256, SMEM_BYTES>>>(x, braw, out);
}